// round 9
// baseline (speedup 1.0000x reference)
#include <cuda_runtime.h>
#include <cuda_fp16.h>
#include <cstdint>

// Problem constants
#define BB   16
#define HH   112
#define WW   112
#define CIN  128
#define FF   256
#define EE   3
#define HO   110
#define WO   110
#define NPIX (BB*HO*WO)          // 193600
#define NPIX_IN (BB*HH*WW)       // 200704
#define KD   1152                // 9*128

// GEMM tiling
#define BM 128
#define BN 128
#define KC 64                    // K-chunk depth (half a tap)
#define NKCH (KD/KC)             // 18
#define NSTAGE 3
#define ASTR 72                  // padded halves per A smem row (144B)
#define BSTR 136                 // padded halves per B smem row (272B)
#define A_STG (BM*ASTR)          // halves per A stage (9216)
#define B_STG (KC*BSTR)          // halves per B stage (8704)

// Dynamic smem layout (bytes)
#define SM_PIX  0                // 128 ints
#define SM_BETA 512              // 128 floats
#define SM_A    1024
#define SM_B    (SM_A + NSTAGE*A_STG*2)
#define SM_TOT  (SM_B + NSTAGE*B_STG*2)   // 108544

// Scratch (device globals: allocation-free rule)
__device__ __half g_xq[(size_t)NPIX_IN * CIN];   // sign(x) as fp16 (+-1)
__device__ float  g_absum[NPIX_IN];              // per-pixel channel |x| sum
__device__ __half g_W[KD * FF];                  // fused weights, K-major [k][f]
__device__ float  g_beta[NPIX];                  // box(|x|)/1152

// ---------------------------------------------------------------------------
// Prep 1: binarize x to fp16 and per-pixel channel abs-sum (one warp/pixel)
// ---------------------------------------------------------------------------
__global__ void prep_x_kernel(const float* __restrict__ x) {
    int warp = (blockIdx.x * blockDim.x + threadIdx.x) >> 5;
    int lane = threadIdx.x & 31;
    if (warp >= NPIX_IN) return;
    const float4 v = *reinterpret_cast<const float4*>(x + (size_t)warp * CIN + lane * 4);
    unsigned s01 = (v.x >= 0.f ? 0x3C00u : 0xBC00u) | ((v.y >= 0.f ? 0x3C00u : 0xBC00u) << 16);
    unsigned s23 = (v.z >= 0.f ? 0x3C00u : 0xBC00u) | ((v.w >= 0.f ? 0x3C00u : 0xBC00u) << 16);
    *reinterpret_cast<uint2*>(g_xq + (size_t)warp * CIN + lane * 4) = make_uint2(s01, s23);
    float a = fabsf(v.x) + fabsf(v.y) + fabsf(v.z) + fabsf(v.w);
    #pragma unroll
    for (int off = 16; off; off >>= 1) a += __shfl_xor_sync(0xffffffffu, a, off);
    if (lane == 0) g_absum[warp] = a;
}

// ---------------------------------------------------------------------------
// Prep 2: fused weight W[k,f] = sum_e alpha[e,f] * sign(K_e[k,f]) in fp16
// ---------------------------------------------------------------------------
__global__ void prep_w_kernel(const float* __restrict__ kern,
                              const float* __restrict__ alphas) {
    int idx = blockIdx.x * blockDim.x + threadIdx.x;   // = k*FF + f
    if (idx >= KD * FF) return;
    int f = idx & (FF - 1);
    float acc = 0.f;
    #pragma unroll
    for (int e = 0; e < EE; ++e) {
        float kv = kern[e * (KD * FF) + idx];
        float a  = alphas[e * FF + f];
        acc += (kv >= 0.f) ? a : -a;
    }
    g_W[idx] = __float2half_rn(acc);
}

// ---------------------------------------------------------------------------
// Prep 3: beta = 3x3 box filter of absum / 1152
// ---------------------------------------------------------------------------
__global__ void prep_beta_kernel() {
    int idx = blockIdx.x * blockDim.x + threadIdx.x;
    if (idx >= NPIX) return;
    int b = idx / (HO * WO);
    int r = idx % (HO * WO);
    int h = r / WO, w = r % WO;
    float s = 0.f;
    #pragma unroll
    for (int dh = 0; dh < 3; ++dh)
        #pragma unroll
        for (int dw = 0; dw < 3; ++dw)
            s += g_absum[(b * HH + h + dh) * WW + (w + dw)];
    g_beta[idx] = s * (1.0f / 1152.0f);
}

// ---------------------------------------------------------------------------
// GEMM: out[p,f] = beta[p] * sum_k xq_patch[p,k] * W[k,f]
// CTA 128x128, 8 warps (2x4), warp tile 64x32, mma.sync m16n8k16 f32 accum.
// 3-stage cp.async multistage pipeline, ONE __syncthreads per K-iteration.
// ---------------------------------------------------------------------------
__global__ void __launch_bounds__(256) gemm_kernel(float* __restrict__ out) {
    extern __shared__ char smem[];
    int*    s_pix  = (int*)(smem + SM_PIX);
    float*  s_beta = (float*)(smem + SM_BETA);
    __half* sA     = (__half*)(smem + SM_A);
    __half* sB     = (__half*)(smem + SM_B);

    const int tid   = threadIdx.x;
    const int mtile = blockIdx.x;
    const int ntile = blockIdx.y;

    if (tid < BM) {
        int p  = mtile * BM + tid;
        int pc = min(p, NPIX - 1);
        int b = pc / (HO * WO);
        int r = pc % (HO * WO);
        int h = r / WO, w = r % WO;
        s_pix[tid]  = ((b * HH + h) * WW + w) * CIN;
        s_beta[tid] = g_beta[pc];
    }
    __syncthreads();

    // Producer addressing (fixed per thread)
    // A: 128 rows x 128B = 1024 x 16B segs; thread -> row tid>>1, segs (tid&1)*4+j
    const int arow = tid >> 1;
    const int aseg0 = (tid & 1) * 4;
    const int apix = s_pix[arow];
    // B: 64 rows x 256B = 1024 x 16B segs; thread -> row tid>>2, segs (tid&3)*4+j
    const int brow = tid >> 2;
    const int bseg0 = (tid & 3) * 4;
    const __half* bsrc_base = g_W + (size_t)brow * FF + ntile * BN + bseg0 * 8;

    auto produce = [&](int c, int buf) {
        int tap  = c >> 1;                             // 2 chunks of 64ch per tap
        int xoff = ((tap / 3) * WW + (tap % 3)) * CIN + (c & 1) * 64 + aseg0 * 8;
        const __half* asrc = g_xq + apix + xoff;
        __half* adst = sA + buf * A_STG + arow * ASTR + aseg0 * 8;
        #pragma unroll
        for (int j = 0; j < 4; ++j) {
            unsigned d = (unsigned)__cvta_generic_to_shared(adst + j * 8);
            asm volatile("cp.async.cg.shared.global [%0], [%1], 16;" :: "r"(d), "l"(asrc + j * 8));
        }
        const __half* bsrc = bsrc_base + (size_t)(c * KC) * FF;
        __half* bdst = sB + buf * B_STG + brow * BSTR + bseg0 * 8;
        #pragma unroll
        for (int j = 0; j < 4; ++j) {
            unsigned d = (unsigned)__cvta_generic_to_shared(bdst + j * 8);
            asm volatile("cp.async.cg.shared.global [%0], [%1], 16;" :: "r"(d), "l"(bsrc + j * 8));
        }
        asm volatile("cp.async.commit_group;\n");
    };

    float acc[4][4][4];
    #pragma unroll
    for (int i = 0; i < 4; ++i)
        #pragma unroll
        for (int j = 0; j < 4; ++j)
            #pragma unroll
            for (int q = 0; q < 4; ++q) acc[i][j][q] = 0.f;

    const int warp = tid >> 5, lane = tid & 31;
    const int wm = (warp & 1) * 64;   // warp M offset
    const int wn = (warp >> 1) * 32;  // warp N offset
    const int lr = lane & 15;
    const int lc = lane >> 4;

    auto compute_tile = [&](int buf) {
        const __half* a_base = sA + buf * A_STG;
        const __half* b_base = sB + buf * B_STG;
        #pragma unroll
        for (int k16 = 0; k16 < KC / 16; ++k16) {
            unsigned a[4][4], bfr[2][4];
            #pragma unroll
            for (int mb = 0; mb < 4; ++mb) {
                unsigned addr = (unsigned)__cvta_generic_to_shared(
                    a_base + (wm + mb * 16 + lr) * ASTR + k16 * 16 + lc * 8);
                asm volatile("ldmatrix.sync.aligned.m8n8.x4.shared.b16 {%0,%1,%2,%3}, [%4];"
                    : "=r"(a[mb][0]), "=r"(a[mb][1]), "=r"(a[mb][2]), "=r"(a[mb][3]) : "r"(addr));
            }
            #pragma unroll
            for (int nb = 0; nb < 2; ++nb) {
                unsigned addr = (unsigned)__cvta_generic_to_shared(
                    b_base + (k16 * 16 + lr) * BSTR + wn + nb * 16 + lc * 8);
                asm volatile("ldmatrix.sync.aligned.m8n8.x4.trans.shared.b16 {%0,%1,%2,%3}, [%4];"
                    : "=r"(bfr[nb][0]), "=r"(bfr[nb][1]), "=r"(bfr[nb][2]), "=r"(bfr[nb][3]) : "r"(addr));
            }
            #pragma unroll
            for (int mb = 0; mb < 4; ++mb)
                #pragma unroll
                for (int nb = 0; nb < 4; ++nb) {
                    unsigned b0 = bfr[nb >> 1][(nb & 1) * 2];
                    unsigned b1 = bfr[nb >> 1][(nb & 1) * 2 + 1];
                    asm volatile("mma.sync.aligned.m16n8k16.row.col.f32.f16.f16.f32 "
                        "{%0,%1,%2,%3}, {%4,%5,%6,%7}, {%8,%9}, {%0,%1,%2,%3};"
                        : "+f"(acc[mb][nb][0]), "+f"(acc[mb][nb][1]),
                          "+f"(acc[mb][nb][2]), "+f"(acc[mb][nb][3])
                        : "r"(a[mb][0]), "r"(a[mb][1]), "r"(a[mb][2]), "r"(a[mb][3]),
                          "r"(b0), "r"(b1));
                }
        }
    };

    // Prologue: stages 0..NSTAGE-2
    produce(0, 0);
    produce(1, 1);

    // Mainloop: one __syncthreads per iteration
    for (int c = 0; c < NKCH; ++c) {
        if (c + NSTAGE - 1 < NKCH) {
            asm volatile("cp.async.wait_group 1;\n");
            __syncthreads();
            produce(c + NSTAGE - 1, (c + NSTAGE - 1) % NSTAGE);
        } else {
            asm volatile("cp.async.wait_group 0;\n");
            __syncthreads();
        }
        compute_tile(c % NSTAGE);
    }

    // Epilogue: scale by beta, write f32
    const int g  = lane >> 2;
    const int l2 = (lane & 3) * 2;
    #pragma unroll
    for (int mb = 0; mb < 4; ++mb) {
        int row0l = wm + mb * 16 + g;
        int p0 = mtile * BM + row0l;
        int p1 = p0 + 8;
        float be0 = s_beta[row0l];
        float be1 = s_beta[row0l + 8];
        #pragma unroll
        for (int nb = 0; nb < 4; ++nb) {
            int col = ntile * BN + wn + nb * 8 + l2;
            if (p0 < NPIX) {
                float2 v = make_float2(acc[mb][nb][0] * be0, acc[mb][nb][1] * be0);
                *reinterpret_cast<float2*>(out + (size_t)p0 * FF + col) = v;
            }
            if (p1 < NPIX) {
                float2 v = make_float2(acc[mb][nb][2] * be1, acc[mb][nb][3] * be1);
                *reinterpret_cast<float2*>(out + (size_t)p1 * FF + col) = v;
            }
        }
    }
}

// ---------------------------------------------------------------------------
extern "C" void kernel_launch(void* const* d_in, const int* in_sizes, int n_in,
                              void* d_out, int out_size) {
    const float* x      = (const float*)d_in[0];
    const float* kern   = (const float*)d_in[1];
    const float* alphas = (const float*)d_in[2];
    float* out = (float*)d_out;

    cudaFuncSetAttribute(gemm_kernel, cudaFuncAttributeMaxDynamicSharedMemorySize, SM_TOT);

    prep_x_kernel<<<NPIX_IN / 8, 256>>>(x);
    prep_w_kernel<<<(KD * FF + 255) / 256, 256>>>(kern, alphas);
    prep_beta_kernel<<<(NPIX + 255) / 256, 256>>>();

    dim3 grid((NPIX + BM - 1) / BM, FF / BN);   // (1513, 2)
    gemm_kernel<<<grid, 256, SM_TOT>>>(out);
}